// round 10
// baseline (speedup 1.0000x reference)
#include <cuda_runtime.h>
#include <cuda_bf16.h>
#include <cstdint>
#include <cstddef>

// ---------------------------------------------------------------------------
// LSTM T=512 B=64 I=H=512 on sm_103 (no tcgen05): mma.sync bf16 hi/lo split.
//   cvt:   x, W_ih -> bf16 hi/lo scratch
//   xproj: x_projT[2048][32768] = W_ih @ x^T   (3-product bf16 split, fp32 acc)
//   rec:   persistent 128-CTA recurrence; reg weights; fragment-ordered image;
//          atomic-free slot barrier (per-CTA release store + v4 poll).
// ---------------------------------------------------------------------------

#define T_STEPS 512
#define BATCH   64
#define HID     512
#define TB      32768              // T*B
#define NROWS   2048               // 4*H gate rows

__device__ __align__(16) __nv_bfloat16 g_xhi[(size_t)TB * HID];
__device__ __align__(16) __nv_bfloat16 g_xlo[(size_t)TB * HID];
__device__ __align__(16) __nv_bfloat16 g_whi[(size_t)NROWS * HID];
__device__ __align__(16) __nv_bfloat16 g_wlo[(size_t)NROWS * HID];
__device__ __align__(16) float         g_xpT[(size_t)NROWS * TB];   // [m][tb]
// fragment-ordered h image: [parity][bh][16384 words]
// blk = (wk*4+kc)*2+part ; word = blk*256 + q*128 + lane*4 + j ; idx = q*4+j
// (ni, reg) = (idx>>1, idx&1)
__device__ __align__(16) uint32_t g_img[2][2][16384];
__device__ __align__(16) uint32_t g_slots[128];    // per-CTA step counters
#define REC_NCTA 128

// ------------------------------ helpers ------------------------------------
__device__ __forceinline__ uint32_t ld_vol_u32(const uint32_t* p) {
    uint32_t v;
    asm volatile("ld.volatile.global.u32 %0, [%1];" : "=r"(v) : "l"(p));
    return v;
}
__device__ __forceinline__ uint4 ld_vol_u4(const uint4* p) {
    uint4 v;
    asm volatile("ld.volatile.global.v4.u32 {%0,%1,%2,%3}, [%4];"
                 : "=r"(v.x), "=r"(v.y), "=r"(v.z), "=r"(v.w) : "l"(p));
    return v;
}
__device__ __forceinline__ void st_vol_u32(uint32_t* p, uint32_t v) {
    asm volatile("st.volatile.global.u32 [%0], %1;" :: "l"(p), "r"(v));
}
__device__ __forceinline__ void fence_gpu() {
    asm volatile("fence.acq_rel.gpu;" ::: "memory");
}
__device__ __forceinline__ uint32_t ld_s32(const char* p) {
    return *reinterpret_cast<const uint32_t*>(p);
}
__device__ __forceinline__ uint4 ldcg_u4(const uint32_t* p) {
    uint4 v;
    asm volatile("ld.global.cg.v4.u32 {%0,%1,%2,%3}, [%4];"
                 : "=r"(v.x), "=r"(v.y), "=r"(v.z), "=r"(v.w) : "l"(p));
    return v;
}
__device__ __forceinline__ void mma_bf16(float (&d)[4], const uint32_t (&a)[4],
                                         const uint32_t (&b)[2]) {
    asm volatile(
        "mma.sync.aligned.m16n8k16.row.col.f32.bf16.bf16.f32 "
        "{%0,%1,%2,%3}, {%4,%5,%6,%7}, {%8,%9}, {%0,%1,%2,%3};\n"
        : "+f"(d[0]), "+f"(d[1]), "+f"(d[2]), "+f"(d[3])
        : "r"(a[0]), "r"(a[1]), "r"(a[2]), "r"(a[3]), "r"(b[0]), "r"(b[1]));
}
// A fragment: rows {r, r+8}, k cols {2tq, 2tq+1, +8} (k-major smem, byte stride S)
__device__ __forceinline__ void ldA(uint32_t (&a)[4], const char* base, int row,
                                    int colb, int S) {
    a[0] = ld_s32(base + (size_t)row * S + colb);
    a[1] = ld_s32(base + (size_t)(row + 8) * S + colb);
    a[2] = ld_s32(base + (size_t)row * S + colb + 16);
    a[3] = ld_s32(base + (size_t)(row + 8) * S + colb + 16);
}
__device__ __forceinline__ void ldB(uint32_t (&b)[2], const char* base, int nrow,
                                    int colb, int S) {
    b[0] = ld_s32(base + (size_t)nrow * S + colb);
    b[1] = ld_s32(base + (size_t)nrow * S + colb + 16);
}
__device__ __forceinline__ uint32_t pack_hi2(float2 v) {
    union { __nv_bfloat162 h2; uint32_t u; } r;
    r.h2.x = __float2bfloat16(v.x);
    r.h2.y = __float2bfloat16(v.y);
    return r.u;
}
__device__ __forceinline__ uint32_t pack_lo2(float2 v) {
    union { __nv_bfloat162 h2; uint32_t u; } r;
    __nv_bfloat16 hx = __float2bfloat16(v.x);
    __nv_bfloat16 hy = __float2bfloat16(v.y);
    r.h2.x = __float2bfloat16(v.x - __bfloat162float(hx));
    r.h2.y = __float2bfloat16(v.y - __bfloat162float(hy));
    return r.u;
}
__device__ __forceinline__ float fast_sigmoid(float x) { return 1.f / (1.f + __expf(-x)); }
__device__ __forceinline__ float fast_tanh(float x) {
    float ax = fabsf(x);
    float t = 1.f - 2.f / (__expf(2.f * ax) + 1.f);
    return copysignf(t, x);
}

// ===========================================================================
// Kernel 0: fp32 -> bf16 hi/lo conversion for x and W_ih
// ===========================================================================
__global__ void cvt_kernel(const float* __restrict__ x, const float* __restrict__ W_ih) {
    const size_t stride = (size_t)gridDim.x * blockDim.x;
    const size_t gid = (size_t)blockIdx.x * blockDim.x + threadIdx.x;
    for (size_t i = gid; i < (size_t)NROWS * HID; i += stride) {
        float v = W_ih[i];
        __nv_bfloat16 h = __float2bfloat16(v);
        g_whi[i] = h;
        g_wlo[i] = __float2bfloat16(v - __bfloat162float(h));
    }
    for (size_t i = gid; i < (size_t)TB * HID; i += stride) {
        float v = x[i];
        __nv_bfloat16 h = __float2bfloat16(v);
        g_xhi[i] = h;
        g_xlo[i] = __float2bfloat16(v - __bfloat162float(h));
    }
}

// ===========================================================================
// Kernel 1: x_projT = W_ih @ X^T.  CTA tile M128 x N128, K-chunks of 64,
// cp.async double buffer. 16 warps, warp tile 32x32. 3-product split.
// smem row: 64 k + 8 pad = 72 elems = 144 B.
// ===========================================================================
#define KC 64
#define S1 144
#define PART1 (128 * S1)       // 18432 B per part tile
#define BUFSZ (4 * PART1)      // A_hi A_lo B_hi B_lo
#define SMEM1 (2 * BUFSZ)      // 147456 B

__device__ __forceinline__ void xp_issue(char* smc, int c, int m0, int n0, int tid) {
    const int buf = c & 1;
    const int kb = c * KC;
    char* base = smc + buf * BUFSZ;
    #pragma unroll
    for (int j = 0; j < 8; j++) {
        const int id = j * 512 + tid;
        const int which = id >> 10;        // 0 A_hi, 1 A_lo, 2 B_hi, 3 B_lo
        const int r = (id >> 3) & 127;
        const int s = id & 7;
        const __nv_bfloat16* src;
        if (which == 0)      src = g_whi + (size_t)(m0 + r) * HID + kb + s * 8;
        else if (which == 1) src = g_wlo + (size_t)(m0 + r) * HID + kb + s * 8;
        else if (which == 2) src = g_xhi + (size_t)(n0 + r) * HID + kb + s * 8;
        else                 src = g_xlo + (size_t)(n0 + r) * HID + kb + s * 8;
        const uint32_t dst =
            (uint32_t)__cvta_generic_to_shared(base + which * PART1 + r * S1 + s * 16);
        asm volatile("cp.async.cg.shared.global [%0], [%1], 16;\n" :: "r"(dst), "l"(src));
    }
    asm volatile("cp.async.commit_group;\n" ::: "memory");
}

__global__ void __launch_bounds__(512, 1) xproj_kernel() {
    extern __shared__ char smc[];
    const int tid = threadIdx.x;
    const int mt = blockIdx.x & 15, nt = blockIdx.x >> 4;
    const int m0 = mt * 128, n0 = nt * 128;
    const int warp = tid >> 5, lane = tid & 31;
    const int wm = warp >> 2, wn = warp & 3;       // 4x4 warp grid of 32x32
    const int g = lane >> 2, tq = lane & 3;

    float acc[2][4][4];
    #pragma unroll
    for (int mi = 0; mi < 2; mi++)
        #pragma unroll
        for (int ni = 0; ni < 4; ni++)
            #pragma unroll
            for (int q = 0; q < 4; q++) acc[mi][ni][q] = 0.f;

    xp_issue(smc, 0, m0, n0, tid);

    for (int c = 0; c < 8; c++) {
        if (c < 7) {
            xp_issue(smc, c + 1, m0, n0, tid);
            asm volatile("cp.async.wait_group %0;\n" :: "n"(1) : "memory");
        } else {
            asm volatile("cp.async.wait_group %0;\n" :: "n"(0) : "memory");
        }
        __syncthreads();

        const char* Ah = smc + (c & 1) * BUFSZ;
        const char* Al = Ah + PART1;
        const char* Bh = Al + PART1;
        const char* Bl = Bh + PART1;

        #pragma unroll
        for (int k16 = 0; k16 < 4; k16++) {
            const int colb = (k16 * 16 + 2 * tq) * 2;
            uint32_t aH[2][4], aL[2][4], bH[4][2], bL[4][2];
            #pragma unroll
            for (int mi = 0; mi < 2; mi++) ldA(aH[mi], Ah, wm * 32 + mi * 16 + g, colb, S1);
            #pragma unroll
            for (int ni = 0; ni < 4; ni++) ldB(bH[ni], Bh, wn * 32 + ni * 8 + g, colb, S1);
            #pragma unroll
            for (int mi = 0; mi < 2; mi++)
                #pragma unroll
                for (int ni = 0; ni < 4; ni++) mma_bf16(acc[mi][ni], aH[mi], bH[ni]);
            #pragma unroll
            for (int mi = 0; mi < 2; mi++) ldA(aL[mi], Al, wm * 32 + mi * 16 + g, colb, S1);
            #pragma unroll
            for (int mi = 0; mi < 2; mi++)
                #pragma unroll
                for (int ni = 0; ni < 4; ni++) mma_bf16(acc[mi][ni], aL[mi], bH[ni]);
            #pragma unroll
            for (int ni = 0; ni < 4; ni++) ldB(bL[ni], Bl, wn * 32 + ni * 8 + g, colb, S1);
            #pragma unroll
            for (int mi = 0; mi < 2; mi++)
                #pragma unroll
                for (int ni = 0; ni < 4; ni++) mma_bf16(acc[mi][ni], aH[mi], bL[ni]);
        }
        __syncthreads();
    }

    // epilogue: D(m, n) -> g_xpT[m][n]
    #pragma unroll
    for (int mi = 0; mi < 2; mi++) {
        const int m = m0 + wm * 32 + mi * 16 + g;
        #pragma unroll
        for (int ni = 0; ni < 4; ni++) {
            const int n = n0 + wn * 32 + ni * 8 + 2 * tq;
            float2 v01 = make_float2(acc[mi][ni][0], acc[mi][ni][1]);
            float2 v23 = make_float2(acc[mi][ni][2], acc[mi][ni][3]);
            *(float2*)(g_xpT + (size_t)m * TB + n) = v01;
            *(float2*)(g_xpT + (size_t)(m + 8) * TB + n) = v23;
        }
    }
}

// ===========================================================================
// Kernel 2: recurrence. 128 CTAs = 64 col-groups x 2 batch-halves, 256 thr.
// Weights in registers. h image fragment-ordered + vectorized (LDG.128).
// Atomic-free barrier: per-CTA slot store (fence.acq_rel.gpu release) + one
// poller warp reading all 128 slots with a single v4 load per lane.
// ===========================================================================
#define OFF_P    0           // 34816 B
#define OFF_HS   34816       // 256 floats = 1024 B
#define OFF_BIAS 35840       // 32 floats (128 B)
#define OFF_BASE 35968
#define SMEM2    36096

__global__ void __launch_bounds__(256, 1)
rec_kernel(const float* __restrict__ W_hh, const float* __restrict__ b_ih,
           const float* __restrict__ b_hh, float* __restrict__ ys) {
    extern __shared__ char smc[];
    const int tid = threadIdx.x;
    const int cg = blockIdx.x >> 1, bh = blockIdx.x & 1;
    const int warp = tid >> 5, lane = tid & 31;
    const int g = lane >> 2, tq = lane & 3;

    float* Pb     = (float*)(smc + OFF_P);
    float* Hs     = (float*)(smc + OFF_HS);
    float* bias_s = (float*)(smc + OFF_BIAS);

    if (tid == 0) {
        // self-relative base: own slot only ever written by this CTA
        *(uint32_t*)(smc + OFF_BASE) = ld_vol_u32(g_slots + blockIdx.x);
    }
    if (tid < 32) {
        const int grow = (tid >> 3) * HID + cg * 8 + (tid & 7);
        bias_s[tid] = __ldg(b_ih + grow) + __ldg(b_hh + grow);
    }

    // ---- preload this lane's weight fragments into registers (once) ----
    const int k0 = warp * 64;
    uint32_t aH[4][2][4], aL[4][2][4];
    #pragma unroll
    for (int kc = 0; kc < 4; kc++) {
        const int k = k0 + kc * 16 + 2 * tq;
        #pragma unroll
        for (int mi = 0; mi < 2; mi++) {
            #pragma unroll
            for (int rr = 0; rr < 2; rr++) {
                const int row = mi * 16 + g + rr * 8;
                const int grow = (row >> 3) * HID + cg * 8 + (row & 7);
                float2 v0 = __ldg((const float2*)(W_hh + (size_t)grow * HID + k));
                float2 v1 = __ldg((const float2*)(W_hh + (size_t)grow * HID + k + 8));
                aH[kc][mi][rr]     = pack_hi2(v0);
                aH[kc][mi][2 + rr] = pack_hi2(v1);
                aL[kc][mi][rr]     = pack_lo2(v0);
                aL[kc][mi][2 + rr] = pack_lo2(v1);
            }
        }
    }
    __syncthreads();
    const uint32_t base = *(const uint32_t*)(smc + OFF_BASE);

    const int cc = tid >> 5;    // hidden col within group (0..7) == warp
    const int bb = tid & 31;    // batch within half
    float cst = 0.f;

    // producer image indexing: h value (n=bb, k=cg*8+cc), hi slot byte offset
    uint32_t pub_off;
    {
        const int k = cg * 8 + cc;
        const int wk = k >> 6, kk = k & 63;
        const int kc = kk >> 4, kpos = kk & 15;
        const int reg = kpos >> 3, r = kpos & 7;
        const int tq2 = r >> 1, hs = r & 1;
        const int ni = bb >> 3, g2 = bb & 7;
        const int lanei = g2 * 4 + tq2;
        const int idx = ni * 2 + reg;           // 0..7
        const int q = idx >> 2, j = idx & 3;
        const uint32_t word = (uint32_t)(((wk * 4 + kc) * 2 + 0) * 256 + q * 128 + lanei * 4 + j);
        pub_off = word * 4 + (uint32_t)hs * 2;  // lo slot at +1024 bytes
    }

    // prefetch x_proj for t=0
    float xpn[4];
    #pragma unroll
    for (int gate = 0; gate < 4; gate++)
        xpn[gate] = __ldg(g_xpT + (size_t)(gate * HID + cg * 8 + cc) * TB + (size_t)bh * 32 + bb);

    for (int t = 0; t < T_STEPS; t++) {
        float xpc[4];
        #pragma unroll
        for (int gate = 0; gate < 4; gate++) xpc[gate] = xpn[gate];

        if (t > 0) {
            // ---- B fragments: 2x LDG.128 per (kc, part), fully coalesced ----
            const uint32_t* img = g_img[(t - 1) & 1][bh];
            uint32_t bH[4][4][2], bL[4][4][2];
            #pragma unroll
            for (int kc = 0; kc < 4; kc++) {
                const uint32_t blk = (uint32_t)(warp * 4 + kc) * 2;
                uint4 h0 = ldcg_u4(img + blk * 256 + lane * 4);
                uint4 h1 = ldcg_u4(img + blk * 256 + 128 + lane * 4);
                uint4 l0 = ldcg_u4(img + (blk + 1) * 256 + lane * 4);
                uint4 l1 = ldcg_u4(img + (blk + 1) * 256 + 128 + lane * 4);
                bH[kc][0][0] = h0.x; bH[kc][0][1] = h0.y;
                bH[kc][1][0] = h0.z; bH[kc][1][1] = h0.w;
                bH[kc][2][0] = h1.x; bH[kc][2][1] = h1.y;
                bH[kc][3][0] = h1.z; bH[kc][3][1] = h1.w;
                bL[kc][0][0] = l0.x; bL[kc][0][1] = l0.y;
                bL[kc][1][0] = l0.z; bL[kc][1][1] = l0.w;
                bL[kc][2][0] = l1.x; bL[kc][2][1] = l1.y;
                bL[kc][3][0] = l1.z; bL[kc][3][1] = l1.w;
            }

            // ---- pure MMA burst (96 issues, register-resident) ----
            float acc[2][4][4];
            #pragma unroll
            for (int mi = 0; mi < 2; mi++)
                #pragma unroll
                for (int ni = 0; ni < 4; ni++)
                    #pragma unroll
                    for (int q = 0; q < 4; q++) acc[mi][ni][q] = 0.f;

            #pragma unroll
            for (int kc = 0; kc < 4; kc++) {
                #pragma unroll
                for (int mi = 0; mi < 2; mi++)
                    #pragma unroll
                    for (int ni = 0; ni < 4; ni++) mma_bf16(acc[mi][ni], aH[kc][mi], bH[kc][ni]);
                #pragma unroll
                for (int mi = 0; mi < 2; mi++)
                    #pragma unroll
                    for (int ni = 0; ni < 4; ni++) mma_bf16(acc[mi][ni], aL[kc][mi], bH[kc][ni]);
                #pragma unroll
                for (int mi = 0; mi < 2; mi++)
                    #pragma unroll
                    for (int ni = 0; ni < 4; ni++) mma_bf16(acc[mi][ni], aH[kc][mi], bL[kc][ni]);
            }

            // partial stores P[warp][m][n] (n-stride 34, even -> aligned float2)
            #pragma unroll
            for (int mi = 0; mi < 2; mi++) {
                #pragma unroll
                for (int ni = 0; ni < 4; ni++) {
                    const int m = mi * 16 + g;
                    const int n = ni * 8 + 2 * tq;
                    *(float2*)(Pb + (size_t)(warp * 32 + m) * 34 + n) =
                        make_float2(acc[mi][ni][0], acc[mi][ni][1]);
                    *(float2*)(Pb + (size_t)(warp * 32 + m + 8) * 34 + n) =
                        make_float2(acc[mi][ni][2], acc[mi][ni][3]);
                }
            }
        }
        __syncthreads();

        // activations: thread = (cc, bb)
        {
            float gv[4];
            #pragma unroll
            for (int gate = 0; gate < 4; gate++) {
                float s = xpc[gate] + bias_s[gate * 8 + cc];
                if (t > 0) {
                    #pragma unroll
                    for (int w = 0; w < 8; w++)
                        s += Pb[(size_t)(w * 32 + gate * 8 + cc) * 34 + bb];
                }
                gv[gate] = s;
            }
            const float ig = fast_sigmoid(gv[0]);
            const float fg = fast_sigmoid(gv[1]);
            const float gg = fast_tanh(gv[2]);
            const float og = fast_sigmoid(gv[3]);
            cst = fg * cst + ig * gg;
            const float h = og * fast_tanh(cst);
            Hs[bb * 8 + cc] = h;

            // publish h into the fragment-ordered image (parity t&1)
            char* imgc = (char*)g_img[t & 1][bh];
            __nv_bfloat16 hh = __float2bfloat16(h);
            __nv_bfloat16 hl = __float2bfloat16(h - __bfloat162float(hh));
            *(__nv_bfloat16*)(imgc + pub_off)        = hh;   // part 0 (hi)
            *(__nv_bfloat16*)(imgc + pub_off + 1024) = hl;   // part 1 (lo)
        }
        __syncthreads();   // all image stores issued block-wide

        // release: publish step counter (no atomics, per-CTA slot)
        if (t < T_STEPS - 1 && tid == 0) {
            fence_gpu();                                   // order image stores
            st_vol_u32(g_slots + blockIdx.x, base + (uint32_t)t + 1u);
        }

        // overlap with other CTAs' arrival: ys store + next-xp prefetch
        if (tid < 64) {
            const int b = tid >> 1, half = tid & 1;
            float4 v = *(float4*)(Hs + b * 8 + half * 4);
            *(float4*)(ys + ((size_t)t * 64 + bh * 32 + b) * HID + cg * 8 + half * 4) = v;
        }
        {
            const int tn = (t + 1 < T_STEPS) ? t + 1 : t;
            const size_t ncol = (size_t)tn * 64 + bh * 32 + bb;
            #pragma unroll
            for (int gate = 0; gate < 4; gate++)
                xpn[gate] = __ldg(g_xpT + (size_t)(gate * HID + cg * 8 + cc) * TB + ncol);
        }

        // wait: warp 0 polls all 128 slots (1 v4 load per lane per iter)
        if (t < T_STEPS - 1) {
            if (warp == 0) {
                const uint32_t tgt = base + (uint32_t)t + 1u;
                const uint4* sp = (const uint4*)g_slots + lane;
                bool ok;
                do {
                    uint4 v = ld_vol_u4(sp);
                    ok = (v.x >= tgt) && (v.y >= tgt) && (v.z >= tgt) && (v.w >= tgt);
                } while (!__all_sync(0xffffffffu, ok));
                fence_gpu();                               // acquire
            }
            __syncthreads();
        }
    }
}

// ===========================================================================
extern "C" void kernel_launch(void* const* d_in, const int* in_sizes, int n_in,
                              void* d_out, int out_size) {
    (void)in_sizes; (void)n_in; (void)out_size;
    const float* x    = (const float*)d_in[0];
    const float* W_ih = (const float*)d_in[1];
    const float* W_hh = (const float*)d_in[2];
    const float* b_ih = (const float*)d_in[3];
    const float* b_hh = (const float*)d_in[4];
    float* ys = (float*)d_out;

    cudaFuncSetAttribute(xproj_kernel, cudaFuncAttributeMaxDynamicSharedMemorySize, SMEM1);
    cudaFuncSetAttribute(rec_kernel,   cudaFuncAttributeMaxDynamicSharedMemorySize, SMEM2);

    cvt_kernel<<<2048, 256>>>(x, W_ih);
    xproj_kernel<<<4096, 512, SMEM1>>>();
    rec_kernel<<<REC_NCTA, 256, SMEM2>>>(W_hh, b_ih, b_hh, ys);
}

// round 11
// speedup vs baseline: 1.4553x; 1.4553x over previous
#include <cuda_runtime.h>
#include <cuda_bf16.h>
#include <cstdint>
#include <cstddef>

// ---------------------------------------------------------------------------
// LSTM T=512 B=64 I=H=512 on sm_103 (no tcgen05): mma.sync bf16 hi/lo split.
//   cvt:   x, W_ih -> bf16 hi/lo scratch
//   xproj: x_projT[2048][32768] = W_ih @ x^T   (3-product bf16 split, fp32 acc)
//   rec:   persistent 128-CTA recurrence; reg weights; fragment-ordered image
//          (uint4 loads); packed coalesced publish; R9 atomic barrier.
// ---------------------------------------------------------------------------

#define T_STEPS 512
#define BATCH   64
#define HID     512
#define TB      32768              // T*B
#define NROWS   2048               // 4*H gate rows

__device__ __align__(16) __nv_bfloat16 g_xhi[(size_t)TB * HID];
__device__ __align__(16) __nv_bfloat16 g_xlo[(size_t)TB * HID];
__device__ __align__(16) __nv_bfloat16 g_whi[(size_t)NROWS * HID];
__device__ __align__(16) __nv_bfloat16 g_wlo[(size_t)NROWS * HID];
__device__ __align__(16) float         g_xpT[(size_t)NROWS * TB];   // [m][tb]
// fragment-ordered h image: [parity][bh][16384 words]
// blk = (wk*4+kc)*2+part ; word = blk*256 + q*128 + lane*4 + j ; idx = q*4+j
// (ni, reg) = (idx>>1, idx&1); word = bf16x2 {k=...+2tq+0, +1} for n=ni*8+g
__device__ __align__(16) uint32_t g_img[2][2][16384];
__device__ unsigned long long g_bar = 0ull;

#define REC_NCTA 128
#define BARS_PER_LAUNCH (511ull * REC_NCTA)

// ------------------------------ helpers ------------------------------------
__device__ __forceinline__ unsigned long long ld_vol_u64(const unsigned long long* p) {
    unsigned long long v;
    asm volatile("ld.volatile.global.u64 %0, [%1];" : "=l"(v) : "l"(p));
    return v;
}
__device__ __forceinline__ void fence_gpu() {
    asm volatile("fence.acq_rel.gpu;" ::: "memory");
}
__device__ __forceinline__ uint32_t ld_s32(const char* p) {
    return *reinterpret_cast<const uint32_t*>(p);
}
__device__ __forceinline__ uint4 ldcg_u4(const uint32_t* p) {
    uint4 v;
    asm volatile("ld.global.cg.v4.u32 {%0,%1,%2,%3}, [%4];"
                 : "=r"(v.x), "=r"(v.y), "=r"(v.z), "=r"(v.w) : "l"(p));
    return v;
}
__device__ __forceinline__ void mma_bf16(float (&d)[4], const uint32_t (&a)[4],
                                         const uint32_t (&b)[2]) {
    asm volatile(
        "mma.sync.aligned.m16n8k16.row.col.f32.bf16.bf16.f32 "
        "{%0,%1,%2,%3}, {%4,%5,%6,%7}, {%8,%9}, {%0,%1,%2,%3};\n"
        : "+f"(d[0]), "+f"(d[1]), "+f"(d[2]), "+f"(d[3])
        : "r"(a[0]), "r"(a[1]), "r"(a[2]), "r"(a[3]), "r"(b[0]), "r"(b[1]));
}
// A fragment: rows {r, r+8}, k cols {2tq, 2tq+1, +8} (k-major smem, byte stride S)
__device__ __forceinline__ void ldA(uint32_t (&a)[4], const char* base, int row,
                                    int colb, int S) {
    a[0] = ld_s32(base + (size_t)row * S + colb);
    a[1] = ld_s32(base + (size_t)(row + 8) * S + colb);
    a[2] = ld_s32(base + (size_t)row * S + colb + 16);
    a[3] = ld_s32(base + (size_t)(row + 8) * S + colb + 16);
}
__device__ __forceinline__ void ldB(uint32_t (&b)[2], const char* base, int nrow,
                                    int colb, int S) {
    b[0] = ld_s32(base + (size_t)nrow * S + colb);
    b[1] = ld_s32(base + (size_t)nrow * S + colb + 16);
}
__device__ __forceinline__ uint32_t pack_hi2(float2 v) {
    union { __nv_bfloat162 h2; uint32_t u; } r;
    r.h2.x = __float2bfloat16(v.x);
    r.h2.y = __float2bfloat16(v.y);
    return r.u;
}
__device__ __forceinline__ uint32_t pack_lo2(float2 v) {
    union { __nv_bfloat162 h2; uint32_t u; } r;
    __nv_bfloat16 hx = __float2bfloat16(v.x);
    __nv_bfloat16 hy = __float2bfloat16(v.y);
    r.h2.x = __float2bfloat16(v.x - __bfloat162float(hx));
    r.h2.y = __float2bfloat16(v.y - __bfloat162float(hy));
    return r.u;
}
__device__ __forceinline__ float fast_sigmoid(float x) { return 1.f / (1.f + __expf(-x)); }
__device__ __forceinline__ float fast_tanh(float x) {
    float ax = fabsf(x);
    float t = 1.f - 2.f / (__expf(2.f * ax) + 1.f);
    return copysignf(t, x);
}

// ===========================================================================
// Kernel 0: fp32 -> bf16 hi/lo conversion for x and W_ih
// ===========================================================================
__global__ void cvt_kernel(const float* __restrict__ x, const float* __restrict__ W_ih) {
    const size_t stride = (size_t)gridDim.x * blockDim.x;
    const size_t gid = (size_t)blockIdx.x * blockDim.x + threadIdx.x;
    for (size_t i = gid; i < (size_t)NROWS * HID; i += stride) {
        float v = W_ih[i];
        __nv_bfloat16 h = __float2bfloat16(v);
        g_whi[i] = h;
        g_wlo[i] = __float2bfloat16(v - __bfloat162float(h));
    }
    for (size_t i = gid; i < (size_t)TB * HID; i += stride) {
        float v = x[i];
        __nv_bfloat16 h = __float2bfloat16(v);
        g_xhi[i] = h;
        g_xlo[i] = __float2bfloat16(v - __bfloat162float(h));
    }
}

// ===========================================================================
// Kernel 1: x_projT = W_ih @ X^T.  CTA tile M128 x N128, K-chunks of 64,
// cp.async double buffer. 16 warps, warp tile 32x32. 3-product split.
// smem row: 64 k + 8 pad = 72 elems = 144 B.
// ===========================================================================
#define KC 64
#define S1 144
#define PART1 (128 * S1)       // 18432 B per part tile
#define BUFSZ (4 * PART1)      // A_hi A_lo B_hi B_lo
#define SMEM1 (2 * BUFSZ)      // 147456 B

__device__ __forceinline__ void xp_issue(char* smc, int c, int m0, int n0, int tid) {
    const int buf = c & 1;
    const int kb = c * KC;
    char* base = smc + buf * BUFSZ;
    #pragma unroll
    for (int j = 0; j < 8; j++) {
        const int id = j * 512 + tid;
        const int which = id >> 10;        // 0 A_hi, 1 A_lo, 2 B_hi, 3 B_lo
        const int r = (id >> 3) & 127;
        const int s = id & 7;
        const __nv_bfloat16* src;
        if (which == 0)      src = g_whi + (size_t)(m0 + r) * HID + kb + s * 8;
        else if (which == 1) src = g_wlo + (size_t)(m0 + r) * HID + kb + s * 8;
        else if (which == 2) src = g_xhi + (size_t)(n0 + r) * HID + kb + s * 8;
        else                 src = g_xlo + (size_t)(n0 + r) * HID + kb + s * 8;
        const uint32_t dst =
            (uint32_t)__cvta_generic_to_shared(base + which * PART1 + r * S1 + s * 16);
        asm volatile("cp.async.cg.shared.global [%0], [%1], 16;\n" :: "r"(dst), "l"(src));
    }
    asm volatile("cp.async.commit_group;\n" ::: "memory");
}

__global__ void __launch_bounds__(512, 1) xproj_kernel() {
    extern __shared__ char smc[];
    const int tid = threadIdx.x;
    const int mt = blockIdx.x & 15, nt = blockIdx.x >> 4;
    const int m0 = mt * 128, n0 = nt * 128;
    const int warp = tid >> 5, lane = tid & 31;
    const int wm = warp >> 2, wn = warp & 3;       // 4x4 warp grid of 32x32
    const int g = lane >> 2, tq = lane & 3;

    float acc[2][4][4];
    #pragma unroll
    for (int mi = 0; mi < 2; mi++)
        #pragma unroll
        for (int ni = 0; ni < 4; ni++)
            #pragma unroll
            for (int q = 0; q < 4; q++) acc[mi][ni][q] = 0.f;

    xp_issue(smc, 0, m0, n0, tid);

    for (int c = 0; c < 8; c++) {
        if (c < 7) {
            xp_issue(smc, c + 1, m0, n0, tid);
            asm volatile("cp.async.wait_group %0;\n" :: "n"(1) : "memory");
        } else {
            asm volatile("cp.async.wait_group %0;\n" :: "n"(0) : "memory");
        }
        __syncthreads();

        const char* Ah = smc + (c & 1) * BUFSZ;
        const char* Al = Ah + PART1;
        const char* Bh = Al + PART1;
        const char* Bl = Bh + PART1;

        #pragma unroll
        for (int k16 = 0; k16 < 4; k16++) {
            const int colb = (k16 * 16 + 2 * tq) * 2;
            uint32_t aH[2][4], aL[2][4], bH[4][2], bL[4][2];
            #pragma unroll
            for (int mi = 0; mi < 2; mi++) ldA(aH[mi], Ah, wm * 32 + mi * 16 + g, colb, S1);
            #pragma unroll
            for (int ni = 0; ni < 4; ni++) ldB(bH[ni], Bh, wn * 32 + ni * 8 + g, colb, S1);
            #pragma unroll
            for (int mi = 0; mi < 2; mi++)
                #pragma unroll
                for (int ni = 0; ni < 4; ni++) mma_bf16(acc[mi][ni], aH[mi], bH[ni]);
            #pragma unroll
            for (int mi = 0; mi < 2; mi++) ldA(aL[mi], Al, wm * 32 + mi * 16 + g, colb, S1);
            #pragma unroll
            for (int mi = 0; mi < 2; mi++)
                #pragma unroll
                for (int ni = 0; ni < 4; ni++) mma_bf16(acc[mi][ni], aL[mi], bH[ni]);
            #pragma unroll
            for (int ni = 0; ni < 4; ni++) ldB(bL[ni], Bl, wn * 32 + ni * 8 + g, colb, S1);
            #pragma unroll
            for (int mi = 0; mi < 2; mi++)
                #pragma unroll
                for (int ni = 0; ni < 4; ni++) mma_bf16(acc[mi][ni], aH[mi], bL[ni]);
        }
        __syncthreads();
    }

    // epilogue: D(m, n) -> g_xpT[m][n]
    #pragma unroll
    for (int mi = 0; mi < 2; mi++) {
        const int m = m0 + wm * 32 + mi * 16 + g;
        #pragma unroll
        for (int ni = 0; ni < 4; ni++) {
            const int n = n0 + wn * 32 + ni * 8 + 2 * tq;
            float2 v01 = make_float2(acc[mi][ni][0], acc[mi][ni][1]);
            float2 v23 = make_float2(acc[mi][ni][2], acc[mi][ni][3]);
            *(float2*)(g_xpT + (size_t)m * TB + n) = v01;
            *(float2*)(g_xpT + (size_t)(m + 8) * TB + n) = v23;
        }
    }
}

// ===========================================================================
// Kernel 2: recurrence. 128 CTAs = 64 col-groups x 2 batch-halves, 256 thr.
// Weights in registers. B fragments via coalesced uint4 loads. Packed publish
// (SMEM gather -> 256 coalesced 4B stores). R9 atomic barrier (leader-only
// cumulative fence + atomicAdd arrive + single-line volatile spin).
// ===========================================================================
#define OFF_P    0           // 34816 B
#define OFF_HS   34816       // 256 floats = 1024 B
#define OFF_BIAS 35840       // 32 floats (128 B)
#define OFF_BASE 35968
#define SMEM2    36096

__global__ void __launch_bounds__(256, 1)
rec_kernel(const float* __restrict__ W_hh, const float* __restrict__ b_ih,
           const float* __restrict__ b_hh, float* __restrict__ ys) {
    extern __shared__ char smc[];
    const int tid = threadIdx.x;
    const int cg = blockIdx.x >> 1, bh = blockIdx.x & 1;
    const int warp = tid >> 5, lane = tid & 31;
    const int g = lane >> 2, tq = lane & 3;

    float* Pb     = (float*)(smc + OFF_P);
    float* Hs     = (float*)(smc + OFF_HS);
    float* bias_s = (float*)(smc + OFF_BIAS);

    if (tid == 0) {
        unsigned long long v = ld_vol_u64(&g_bar);
        *(unsigned long long*)(smc + OFF_BASE) = (v / BARS_PER_LAUNCH) * BARS_PER_LAUNCH;
    }
    if (tid < 32) {
        const int grow = (tid >> 3) * HID + cg * 8 + (tid & 7);
        bias_s[tid] = __ldg(b_ih + grow) + __ldg(b_hh + grow);
    }

    // ---- preload this lane's weight fragments into registers (once) ----
    const int k0 = warp * 64;
    uint32_t aH[4][2][4], aL[4][2][4];
    #pragma unroll
    for (int kc = 0; kc < 4; kc++) {
        const int k = k0 + kc * 16 + 2 * tq;
        #pragma unroll
        for (int mi = 0; mi < 2; mi++) {
            #pragma unroll
            for (int rr = 0; rr < 2; rr++) {
                const int row = mi * 16 + g + rr * 8;
                const int grow = (row >> 3) * HID + cg * 8 + (row & 7);
                float2 v0 = __ldg((const float2*)(W_hh + (size_t)grow * HID + k));
                float2 v1 = __ldg((const float2*)(W_hh + (size_t)grow * HID + k + 8));
                aH[kc][mi][rr]     = pack_hi2(v0);
                aH[kc][mi][2 + rr] = pack_hi2(v1);
                aL[kc][mi][rr]     = pack_lo2(v0);
                aL[kc][mi][2 + rr] = pack_lo2(v1);
            }
        }
    }
    __syncthreads();
    const unsigned long long base = *(const unsigned long long*)(smc + OFF_BASE);

    const int cc = tid >> 5;    // hidden col within group (0..7) == warp
    const int bb = tid & 31;    // batch within half
    float cst = 0.f;

    // ---- packed-publish mapping for this thread (one image word/step) ----
    // CTA owns k in [cg*8, cg*8+8): wk = cg>>3, kc_abs = (cg&7)>>1, R = cg&1.
    // thread -> (part, q, jj, lanei); word = blk*256 + q*128 + lanei*4 + (2jj+R)
    // value pair: bb_p = (q*2+jj)*8 + (lanei>>2), cc0 = 2*(lanei&3)
    uint32_t pub_word;
    int pub_src;
    bool pub_lo;
    {
        const int part = tid >> 7;
        const int rem = tid & 127;
        const int q  = rem >> 6;
        const int jj = (rem >> 5) & 1;
        const int lanei = rem & 31;
        const int R = cg & 1;
        const uint32_t blk = (uint32_t)(((cg >> 3) * 4 + ((cg & 7) >> 1)) * 2 + part);
        pub_word = blk * 256u + (uint32_t)q * 128u + (uint32_t)lanei * 4u
                 + (uint32_t)(2 * jj + R);
        const int bb_p = (q * 2 + jj) * 8 + (lanei >> 2);
        pub_src = bb_p * 8 + 2 * (lanei & 3);
        pub_lo = (part != 0);
    }

    // prefetch x_proj for t=0
    float xpn[4];
    #pragma unroll
    for (int gate = 0; gate < 4; gate++)
        xpn[gate] = __ldg(g_xpT + (size_t)(gate * HID + cg * 8 + cc) * TB + (size_t)bh * 32 + bb);

    for (int t = 0; t < T_STEPS; t++) {
        float xpc[4];
        #pragma unroll
        for (int gate = 0; gate < 4; gate++) xpc[gate] = xpn[gate];

        if (t > 0) {
            // ---- B fragments: 2x LDG.128 per (kc, part), fully coalesced ----
            const uint32_t* img = g_img[(t - 1) & 1][bh];
            uint32_t bH[4][4][2], bL[4][4][2];
            #pragma unroll
            for (int kc = 0; kc < 4; kc++) {
                const uint32_t blk = (uint32_t)(warp * 4 + kc) * 2;
                uint4 h0 = ldcg_u4(img + blk * 256 + lane * 4);
                uint4 h1 = ldcg_u4(img + blk * 256 + 128 + lane * 4);
                uint4 l0 = ldcg_u4(img + (blk + 1) * 256 + lane * 4);
                uint4 l1 = ldcg_u4(img + (blk + 1) * 256 + 128 + lane * 4);
                bH[kc][0][0] = h0.x; bH[kc][0][1] = h0.y;
                bH[kc][1][0] = h0.z; bH[kc][1][1] = h0.w;
                bH[kc][2][0] = h1.x; bH[kc][2][1] = h1.y;
                bH[kc][3][0] = h1.z; bH[kc][3][1] = h1.w;
                bL[kc][0][0] = l0.x; bL[kc][0][1] = l0.y;
                bL[kc][1][0] = l0.z; bL[kc][1][1] = l0.w;
                bL[kc][2][0] = l1.x; bL[kc][2][1] = l1.y;
                bL[kc][3][0] = l1.z; bL[kc][3][1] = l1.w;
            }

            // ---- pure MMA burst (96 issues, register-resident) ----
            float acc[2][4][4];
            #pragma unroll
            for (int mi = 0; mi < 2; mi++)
                #pragma unroll
                for (int ni = 0; ni < 4; ni++)
                    #pragma unroll
                    for (int q = 0; q < 4; q++) acc[mi][ni][q] = 0.f;

            #pragma unroll
            for (int kc = 0; kc < 4; kc++) {
                #pragma unroll
                for (int mi = 0; mi < 2; mi++)
                    #pragma unroll
                    for (int ni = 0; ni < 4; ni++) mma_bf16(acc[mi][ni], aH[kc][mi], bH[kc][ni]);
                #pragma unroll
                for (int mi = 0; mi < 2; mi++)
                    #pragma unroll
                    for (int ni = 0; ni < 4; ni++) mma_bf16(acc[mi][ni], aL[kc][mi], bH[kc][ni]);
                #pragma unroll
                for (int mi = 0; mi < 2; mi++)
                    #pragma unroll
                    for (int ni = 0; ni < 4; ni++) mma_bf16(acc[mi][ni], aH[kc][mi], bL[kc][ni]);
            }

            // partial stores P[warp][m][n] (n-stride 34, even -> aligned float2)
            #pragma unroll
            for (int mi = 0; mi < 2; mi++) {
                #pragma unroll
                for (int ni = 0; ni < 4; ni++) {
                    const int m = mi * 16 + g;
                    const int n = ni * 8 + 2 * tq;
                    *(float2*)(Pb + (size_t)(warp * 32 + m) * 34 + n) =
                        make_float2(acc[mi][ni][0], acc[mi][ni][1]);
                    *(float2*)(Pb + (size_t)(warp * 32 + m + 8) * 34 + n) =
                        make_float2(acc[mi][ni][2], acc[mi][ni][3]);
                }
            }
        }
        __syncthreads();

        // activations: thread = (cc, bb); write h ONLY to smem (fast path)
        {
            float gv[4];
            #pragma unroll
            for (int gate = 0; gate < 4; gate++) {
                float s = xpc[gate] + bias_s[gate * 8 + cc];
                if (t > 0) {
                    #pragma unroll
                    for (int w = 0; w < 8; w++)
                        s += Pb[(size_t)(w * 32 + gate * 8 + cc) * 34 + bb];
                }
                gv[gate] = s;
            }
            const float ig = fast_sigmoid(gv[0]);
            const float fg = fast_sigmoid(gv[1]);
            const float gg = fast_tanh(gv[2]);
            const float og = fast_sigmoid(gv[3]);
            cst = fg * cst + ig * gg;
            Hs[bb * 8 + cc] = og * fast_tanh(cst);
        }
        __syncthreads();

        // packed publish: 1 LDS.64 + 1 coalesced 4B store per thread
        if (t < T_STEPS - 1) {
            float2 hv = *(const float2*)(Hs + pub_src);
            const uint32_t w = pub_lo ? pack_lo2(hv) : pack_hi2(hv);
            g_img[t & 1][bh][pub_word] = w;
        }
        __syncthreads();   // all publish stores done CTA-wide (for cumulativity)

        // arrive: leader-only cumulative fence + atomic (light, ~1cyc/op at LTS)
        if (t < T_STEPS - 1 && tid == 0) {
            fence_gpu();
            atomicAdd(&g_bar, 1ull);
        }

        // overlap with other CTAs' arrival: ys store + next-xp prefetch
        if (tid < 64) {
            const int b = tid >> 1, half = tid & 1;
            float4 v = *(float4*)(Hs + b * 8 + half * 4);
            *(float4*)(ys + ((size_t)t * 64 + bh * 32 + b) * HID + cg * 8 + half * 4) = v;
        }
        {
            const int tn = (t + 1 < T_STEPS) ? t + 1 : t;
            const size_t ncol = (size_t)tn * 64 + bh * 32 + bb;
            #pragma unroll
            for (int gate = 0; gate < 4; gate++)
                xpn[gate] = __ldg(g_xpT + (size_t)(gate * HID + cg * 8 + cc) * TB + ncol);
        }

        // wait: single leader polls one u64 line
        if (t < T_STEPS - 1) {
            if (tid == 0) {
                const unsigned long long tgt =
                    base + (unsigned long long)(t + 1) * REC_NCTA;
                while (ld_vol_u64(&g_bar) < tgt) { __nanosleep(32); }
                fence_gpu();
            }
            __syncthreads();
        }
    }
}

// ===========================================================================
extern "C" void kernel_launch(void* const* d_in, const int* in_sizes, int n_in,
                              void* d_out, int out_size) {
    (void)in_sizes; (void)n_in; (void)out_size;
    const float* x    = (const float*)d_in[0];
    const float* W_ih = (const float*)d_in[1];
    const float* W_hh = (const float*)d_in[2];
    const float* b_ih = (const float*)d_in[3];
    const float* b_hh = (const float*)d_in[4];
    float* ys = (float*)d_out;

    cudaFuncSetAttribute(xproj_kernel, cudaFuncAttributeMaxDynamicSharedMemorySize, SMEM1);
    cudaFuncSetAttribute(rec_kernel,   cudaFuncAttributeMaxDynamicSharedMemorySize, SMEM2);

    cvt_kernel<<<2048, 256>>>(x, W_ih);
    xproj_kernel<<<4096, 512, SMEM1>>>();
    rec_kernel<<<REC_NCTA, 256, SMEM2>>>(W_hh, b_ih, b_hh, ys);
}

// round 12
// speedup vs baseline: 1.4870x; 1.0218x over previous
#include <cuda_runtime.h>
#include <cuda_bf16.h>
#include <cstdint>
#include <cstddef>

// ---------------------------------------------------------------------------
// LSTM T=512 B=64 I=H=512 on sm_103 (no tcgen05): mma.sync bf16 hi/lo split.
//   cvt:   x, W_ih -> bf16 hi/lo scratch
//   xproj: x_projT = W_ih @ X^T  (3-product bf16 split, ldmatrix fragment loads)
//   rec:   persistent 128-CTA recurrence; reg weights; fragment-ordered image;
//          packed publish; per-batch-half (64-CTA) atomic barriers.
// ---------------------------------------------------------------------------

#define T_STEPS 512
#define BATCH   64
#define HID     512
#define TB      32768              // T*B
#define NROWS   2048               // 4*H gate rows

__device__ __align__(16) __nv_bfloat16 g_xhi[(size_t)TB * HID];
__device__ __align__(16) __nv_bfloat16 g_xlo[(size_t)TB * HID];
__device__ __align__(16) __nv_bfloat16 g_whi[(size_t)NROWS * HID];
__device__ __align__(16) __nv_bfloat16 g_wlo[(size_t)NROWS * HID];
__device__ __align__(16) float         g_xpT[(size_t)NROWS * TB];   // [m][tb]
// fragment-ordered h image: [parity][bh][16384 words]
__device__ __align__(16) uint32_t g_img[2][2][16384];
// per-batch-half barrier counters (128B apart to avoid line sharing)
__device__ __align__(16) unsigned long long g_bar2[32];

#define REC_NCTA 128
#define GRP_CTAS 64
#define BARS_PER_LAUNCH (511ull * GRP_CTAS)

// ------------------------------ helpers ------------------------------------
__device__ __forceinline__ unsigned long long ld_vol_u64(const unsigned long long* p) {
    unsigned long long v;
    asm volatile("ld.volatile.global.u64 %0, [%1];" : "=l"(v) : "l"(p));
    return v;
}
__device__ __forceinline__ void fence_gpu() {
    asm volatile("fence.acq_rel.gpu;" ::: "memory");
}
__device__ __forceinline__ uint4 ldcg_u4(const uint32_t* p) {
    uint4 v;
    asm volatile("ld.global.cg.v4.u32 {%0,%1,%2,%3}, [%4];"
                 : "=r"(v.x), "=r"(v.y), "=r"(v.z), "=r"(v.w) : "l"(p));
    return v;
}
__device__ __forceinline__ void ldsm_x4(uint32_t (&r)[4], uint32_t saddr) {
    asm volatile("ldmatrix.sync.aligned.m8n8.x4.shared.b16 {%0,%1,%2,%3}, [%4];"
                 : "=r"(r[0]), "=r"(r[1]), "=r"(r[2]), "=r"(r[3]) : "r"(saddr));
}
__device__ __forceinline__ void mma_bf16(float (&d)[4], const uint32_t (&a)[4],
                                         const uint32_t (&b)[2]) {
    asm volatile(
        "mma.sync.aligned.m16n8k16.row.col.f32.bf16.bf16.f32 "
        "{%0,%1,%2,%3}, {%4,%5,%6,%7}, {%8,%9}, {%0,%1,%2,%3};\n"
        : "+f"(d[0]), "+f"(d[1]), "+f"(d[2]), "+f"(d[3])
        : "r"(a[0]), "r"(a[1]), "r"(a[2]), "r"(a[3]), "r"(b[0]), "r"(b[1]));
}
__device__ __forceinline__ uint32_t pack_hi2(float2 v) {
    union { __nv_bfloat162 h2; uint32_t u; } r;
    r.h2.x = __float2bfloat16(v.x);
    r.h2.y = __float2bfloat16(v.y);
    return r.u;
}
__device__ __forceinline__ uint32_t pack_lo2(float2 v) {
    union { __nv_bfloat162 h2; uint32_t u; } r;
    __nv_bfloat16 hx = __float2bfloat16(v.x);
    __nv_bfloat16 hy = __float2bfloat16(v.y);
    r.h2.x = __float2bfloat16(v.x - __bfloat162float(hx));
    r.h2.y = __float2bfloat16(v.y - __bfloat162float(hy));
    return r.u;
}
__device__ __forceinline__ float fast_sigmoid(float x) { return 1.f / (1.f + __expf(-x)); }
__device__ __forceinline__ float fast_tanh(float x) {
    float ax = fabsf(x);
    float t = 1.f - 2.f / (__expf(2.f * ax) + 1.f);
    return copysignf(t, x);
}

// ===========================================================================
// Kernel 0: fp32 -> bf16 hi/lo conversion for x and W_ih
// ===========================================================================
__global__ void cvt_kernel(const float* __restrict__ x, const float* __restrict__ W_ih) {
    const size_t stride = (size_t)gridDim.x * blockDim.x;
    const size_t gid = (size_t)blockIdx.x * blockDim.x + threadIdx.x;
    for (size_t i = gid; i < (size_t)NROWS * HID; i += stride) {
        float v = W_ih[i];
        __nv_bfloat16 h = __float2bfloat16(v);
        g_whi[i] = h;
        g_wlo[i] = __float2bfloat16(v - __bfloat162float(h));
    }
    for (size_t i = gid; i < (size_t)TB * HID; i += stride) {
        float v = x[i];
        __nv_bfloat16 h = __float2bfloat16(v);
        g_xhi[i] = h;
        g_xlo[i] = __float2bfloat16(v - __bfloat162float(h));
    }
}

// ===========================================================================
// Kernel 1: x_projT = W_ih @ X^T.  CTA tile M128 x N128, K-chunks of 64,
// cp.async double buffer. 16 warps, warp tile 32x32. 3-product split.
// Fragment loads via ldmatrix.x4 (8 LDSM + 24 MMA per k16, was 32 LDS + 24).
// smem row: 64 k + 8 pad = 72 elems = 144 B (LDSM rows stride 9x16B -> no
// 16B-bank conflicts).
// ===========================================================================
#define KC 64
#define S1 144
#define PART1 (128 * S1)       // 18432 B per part tile
#define BUFSZ (4 * PART1)      // A_hi A_lo B_hi B_lo
#define SMEM1 (2 * BUFSZ)      // 147456 B

__device__ __forceinline__ void xp_issue(char* smc, int c, int m0, int n0, int tid) {
    const int buf = c & 1;
    const int kb = c * KC;
    char* base = smc + buf * BUFSZ;
    #pragma unroll
    for (int j = 0; j < 8; j++) {
        const int id = j * 512 + tid;
        const int which = id >> 10;        // 0 A_hi, 1 A_lo, 2 B_hi, 3 B_lo
        const int r = (id >> 3) & 127;
        const int s = id & 7;
        const __nv_bfloat16* src;
        if (which == 0)      src = g_whi + (size_t)(m0 + r) * HID + kb + s * 8;
        else if (which == 1) src = g_wlo + (size_t)(m0 + r) * HID + kb + s * 8;
        else if (which == 2) src = g_xhi + (size_t)(n0 + r) * HID + kb + s * 8;
        else                 src = g_xlo + (size_t)(n0 + r) * HID + kb + s * 8;
        const uint32_t dst =
            (uint32_t)__cvta_generic_to_shared(base + which * PART1 + r * S1 + s * 16);
        asm volatile("cp.async.cg.shared.global [%0], [%1], 16;\n" :: "r"(dst), "l"(src));
    }
    asm volatile("cp.async.commit_group;\n" ::: "memory");
}

__global__ void __launch_bounds__(512, 1) xproj_kernel() {
    extern __shared__ char smc[];
    const int tid = threadIdx.x;
    const int mt = blockIdx.x & 15, nt = blockIdx.x >> 4;
    const int m0 = mt * 128, n0 = nt * 128;
    const int warp = tid >> 5, lane = tid & 31;
    const int wm = warp >> 2, wn = warp & 3;       // 4x4 warp grid of 32x32

    // ldmatrix per-lane row-address offsets (within a part tile, bytes)
    const int lq = lane & 7;
    const int qa_r = ((lane >> 3) & 1) * 8;        // A: reg pair selects row+8
    const int qa_c = ((lane >> 4) & 1) * 16;       // A: upper regs select k+8
    const int qb_r = ((lane >> 4) & 1) * 8;        // B: upper regs select n+8
    const int qb_c = ((lane >> 3) & 1) * 16;       // B: reg pair selects k+8
    uint32_t aOff[2], bOff[2];
    #pragma unroll
    for (int mi = 0; mi < 2; mi++)
        aOff[mi] = (uint32_t)((wm * 32 + mi * 16 + lq + qa_r) * S1 + qa_c);
    #pragma unroll
    for (int p = 0; p < 2; p++)
        bOff[p] = (uint32_t)((wn * 32 + p * 16 + lq + qb_r) * S1 + qb_c);

    float acc[2][4][4];
    #pragma unroll
    for (int mi = 0; mi < 2; mi++)
        #pragma unroll
        for (int ni = 0; ni < 4; ni++)
            #pragma unroll
            for (int q = 0; q < 4; q++) acc[mi][ni][q] = 0.f;

    xp_issue(smc, 0, m0, n0, tid);

    for (int c = 0; c < 8; c++) {
        if (c < 7) {
            xp_issue(smc, c + 1, m0, n0, tid);
            asm volatile("cp.async.wait_group %0;\n" :: "n"(1) : "memory");
        } else {
            asm volatile("cp.async.wait_group %0;\n" :: "n"(0) : "memory");
        }
        __syncthreads();

        char* bufb = smc + (c & 1) * BUFSZ;
        const uint32_t sAh = (uint32_t)__cvta_generic_to_shared(bufb);
        const uint32_t sAl = sAh + PART1;
        const uint32_t sBh = sAl + PART1;
        const uint32_t sBl = sBh + PART1;

        #pragma unroll
        for (int k16 = 0; k16 < 4; k16++) {
            const uint32_t cb = (uint32_t)k16 * 32;
            uint32_t aH[2][4], aL[2][4], bHp[2][4], bLp[2][4];
            #pragma unroll
            for (int mi = 0; mi < 2; mi++) ldsm_x4(aH[mi], sAh + aOff[mi] + cb);
            #pragma unroll
            for (int p = 0; p < 2; p++)   ldsm_x4(bHp[p], sBh + bOff[p] + cb);
            // bH[ni][reg]: x4 regs = {b(2p)[0], b(2p)[1], b(2p+1)[0], b(2p+1)[1]}
            uint32_t bH[4][2], bL[4][2];
            #pragma unroll
            for (int p = 0; p < 2; p++) {
                bH[2 * p][0] = bHp[p][0]; bH[2 * p][1] = bHp[p][1];
                bH[2 * p + 1][0] = bHp[p][2]; bH[2 * p + 1][1] = bHp[p][3];
            }
            #pragma unroll
            for (int mi = 0; mi < 2; mi++)
                #pragma unroll
                for (int ni = 0; ni < 4; ni++) mma_bf16(acc[mi][ni], aH[mi], bH[ni]);
            #pragma unroll
            for (int mi = 0; mi < 2; mi++) ldsm_x4(aL[mi], sAl + aOff[mi] + cb);
            #pragma unroll
            for (int mi = 0; mi < 2; mi++)
                #pragma unroll
                for (int ni = 0; ni < 4; ni++) mma_bf16(acc[mi][ni], aL[mi], bH[ni]);
            #pragma unroll
            for (int p = 0; p < 2; p++)   ldsm_x4(bLp[p], sBl + bOff[p] + cb);
            #pragma unroll
            for (int p = 0; p < 2; p++) {
                bL[2 * p][0] = bLp[p][0]; bL[2 * p][1] = bLp[p][1];
                bL[2 * p + 1][0] = bLp[p][2]; bL[2 * p + 1][1] = bLp[p][3];
            }
            #pragma unroll
            for (int mi = 0; mi < 2; mi++)
                #pragma unroll
                for (int ni = 0; ni < 4; ni++) mma_bf16(acc[mi][ni], aH[mi], bL[ni]);
        }
        __syncthreads();
    }

    // epilogue: D(m, n) -> g_xpT[m][n]
    const int g = lane >> 2, tq = lane & 3;
    #pragma unroll
    for (int mi = 0; mi < 2; mi++) {
        const int m = m0 + wm * 32 + mi * 16 + g;
        #pragma unroll
        for (int ni = 0; ni < 4; ni++) {
            const int n = n0 + wn * 32 + ni * 8 + 2 * tq;
            float2 v01 = make_float2(acc[mi][ni][0], acc[mi][ni][1]);
            float2 v23 = make_float2(acc[mi][ni][2], acc[mi][ni][3]);
            *(float2*)(g_xpT + (size_t)m * TB + n) = v01;
            *(float2*)(g_xpT + (size_t)(m + 8) * TB + n) = v23;
        }
    }
}

// ===========================================================================
// Kernel 2: recurrence. 128 CTAs = 64 col-groups x 2 batch-halves, 256 thr.
// Weights in registers. B fragments via coalesced uint4 loads. Packed publish.
// Per-batch-half barrier: 64 arrivals per counter, independent halves.
// ===========================================================================
#define OFF_P    0           // 34816 B
#define OFF_HS   34816       // 256 floats = 1024 B
#define OFF_BIAS 35840       // 32 floats (128 B)
#define OFF_BASE 35968
#define SMEM2    36096

__global__ void __launch_bounds__(256, 1)
rec_kernel(const float* __restrict__ W_hh, const float* __restrict__ b_ih,
           const float* __restrict__ b_hh, float* __restrict__ ys) {
    extern __shared__ char smc[];
    const int tid = threadIdx.x;
    const int cg = blockIdx.x >> 1, bh = blockIdx.x & 1;
    const int warp = tid >> 5, lane = tid & 31;
    const int g = lane >> 2, tq = lane & 3;

    float* Pb     = (float*)(smc + OFF_P);
    float* Hs     = (float*)(smc + OFF_HS);
    float* bias_s = (float*)(smc + OFF_BIAS);

    unsigned long long* barp = &g_bar2[bh * 16];

    if (tid == 0) {
        unsigned long long v = ld_vol_u64(barp);
        *(unsigned long long*)(smc + OFF_BASE) = (v / BARS_PER_LAUNCH) * BARS_PER_LAUNCH;
    }
    if (tid < 32) {
        const int grow = (tid >> 3) * HID + cg * 8 + (tid & 7);
        bias_s[tid] = __ldg(b_ih + grow) + __ldg(b_hh + grow);
    }

    // ---- preload this lane's weight fragments into registers (once) ----
    const int k0 = warp * 64;
    uint32_t aH[4][2][4], aL[4][2][4];
    #pragma unroll
    for (int kc = 0; kc < 4; kc++) {
        const int k = k0 + kc * 16 + 2 * tq;
        #pragma unroll
        for (int mi = 0; mi < 2; mi++) {
            #pragma unroll
            for (int rr = 0; rr < 2; rr++) {
                const int row = mi * 16 + g + rr * 8;
                const int grow = (row >> 3) * HID + cg * 8 + (row & 7);
                float2 v0 = __ldg((const float2*)(W_hh + (size_t)grow * HID + k));
                float2 v1 = __ldg((const float2*)(W_hh + (size_t)grow * HID + k + 8));
                aH[kc][mi][rr]     = pack_hi2(v0);
                aH[kc][mi][2 + rr] = pack_hi2(v1);
                aL[kc][mi][rr]     = pack_lo2(v0);
                aL[kc][mi][2 + rr] = pack_lo2(v1);
            }
        }
    }
    __syncthreads();
    const unsigned long long base = *(const unsigned long long*)(smc + OFF_BASE);

    const int cc = tid >> 5;    // hidden col within group (0..7) == warp
    const int bb = tid & 31;    // batch within half
    float cst = 0.f;

    // ---- packed-publish mapping for this thread (one image word/step) ----
    uint32_t pub_word;
    int pub_src;
    bool pub_lo;
    {
        const int part = tid >> 7;
        const int rem = tid & 127;
        const int q  = rem >> 6;
        const int jj = (rem >> 5) & 1;
        const int lanei = rem & 31;
        const int R = cg & 1;
        const uint32_t blk = (uint32_t)(((cg >> 3) * 4 + ((cg & 7) >> 1)) * 2 + part);
        pub_word = blk * 256u + (uint32_t)q * 128u + (uint32_t)lanei * 4u
                 + (uint32_t)(2 * jj + R);
        const int bb_p = (q * 2 + jj) * 8 + (lanei >> 2);
        pub_src = bb_p * 8 + 2 * (lanei & 3);
        pub_lo = (part != 0);
    }

    // prefetch x_proj for t=0
    float xpn[4];
    #pragma unroll
    for (int gate = 0; gate < 4; gate++)
        xpn[gate] = __ldg(g_xpT + (size_t)(gate * HID + cg * 8 + cc) * TB + (size_t)bh * 32 + bb);

    for (int t = 0; t < T_STEPS; t++) {
        float xpc[4];
        #pragma unroll
        for (int gate = 0; gate < 4; gate++) xpc[gate] = xpn[gate];

        if (t > 0) {
            // ---- B fragments: 2x LDG.128 per (kc, part), fully coalesced ----
            const uint32_t* img = g_img[(t - 1) & 1][bh];
            uint32_t bH[4][4][2], bL[4][4][2];
            #pragma unroll
            for (int kc = 0; kc < 4; kc++) {
                const uint32_t blk = (uint32_t)(warp * 4 + kc) * 2;
                uint4 h0 = ldcg_u4(img + blk * 256 + lane * 4);
                uint4 h1 = ldcg_u4(img + blk * 256 + 128 + lane * 4);
                uint4 l0 = ldcg_u4(img + (blk + 1) * 256 + lane * 4);
                uint4 l1 = ldcg_u4(img + (blk + 1) * 256 + 128 + lane * 4);
                bH[kc][0][0] = h0.x; bH[kc][0][1] = h0.y;
                bH[kc][1][0] = h0.z; bH[kc][1][1] = h0.w;
                bH[kc][2][0] = h1.x; bH[kc][2][1] = h1.y;
                bH[kc][3][0] = h1.z; bH[kc][3][1] = h1.w;
                bL[kc][0][0] = l0.x; bL[kc][0][1] = l0.y;
                bL[kc][1][0] = l0.z; bL[kc][1][1] = l0.w;
                bL[kc][2][0] = l1.x; bL[kc][2][1] = l1.y;
                bL[kc][3][0] = l1.z; bL[kc][3][1] = l1.w;
            }

            // ---- pure MMA burst (96 issues, register-resident) ----
            float acc[2][4][4];
            #pragma unroll
            for (int mi = 0; mi < 2; mi++)
                #pragma unroll
                for (int ni = 0; ni < 4; ni++)
                    #pragma unroll
                    for (int q = 0; q < 4; q++) acc[mi][ni][q] = 0.f;

            #pragma unroll
            for (int kc = 0; kc < 4; kc++) {
                #pragma unroll
                for (int mi = 0; mi < 2; mi++)
                    #pragma unroll
                    for (int ni = 0; ni < 4; ni++) mma_bf16(acc[mi][ni], aH[kc][mi], bH[kc][ni]);
                #pragma unroll
                for (int mi = 0; mi < 2; mi++)
                    #pragma unroll
                    for (int ni = 0; ni < 4; ni++) mma_bf16(acc[mi][ni], aL[kc][mi], bH[kc][ni]);
                #pragma unroll
                for (int mi = 0; mi < 2; mi++)
                    #pragma unroll
                    for (int ni = 0; ni < 4; ni++) mma_bf16(acc[mi][ni], aH[kc][mi], bL[kc][ni]);
            }

            // partial stores P[warp][m][n] (n-stride 34, even -> aligned float2)
            #pragma unroll
            for (int mi = 0; mi < 2; mi++) {
                #pragma unroll
                for (int ni = 0; ni < 4; ni++) {
                    const int m = mi * 16 + g;
                    const int n = ni * 8 + 2 * tq;
                    *(float2*)(Pb + (size_t)(warp * 32 + m) * 34 + n) =
                        make_float2(acc[mi][ni][0], acc[mi][ni][1]);
                    *(float2*)(Pb + (size_t)(warp * 32 + m + 8) * 34 + n) =
                        make_float2(acc[mi][ni][2], acc[mi][ni][3]);
                }
            }
        }
        __syncthreads();

        // activations: thread = (cc, bb); write h ONLY to smem (fast path)
        {
            float gv[4];
            #pragma unroll
            for (int gate = 0; gate < 4; gate++) {
                float s = xpc[gate] + bias_s[gate * 8 + cc];
                if (t > 0) {
                    #pragma unroll
                    for (int w = 0; w < 8; w++)
                        s += Pb[(size_t)(w * 32 + gate * 8 + cc) * 34 + bb];
                }
                gv[gate] = s;
            }
            const float ig = fast_sigmoid(gv[0]);
            const float fg = fast_sigmoid(gv[1]);
            const float gg = fast_tanh(gv[2]);
            const float og = fast_sigmoid(gv[3]);
            cst = fg * cst + ig * gg;
            Hs[bb * 8 + cc] = og * fast_tanh(cst);
        }
        __syncthreads();

        // packed publish: 1 LDS.64 + 1 coalesced 4B store per thread
        if (t < T_STEPS - 1) {
            float2 hv = *(const float2*)(Hs + pub_src);
            const uint32_t w = pub_lo ? pack_lo2(hv) : pack_hi2(hv);
            g_img[t & 1][bh][pub_word] = w;
        }
        __syncthreads();   // all publish stores done CTA-wide (for cumulativity)

        // arrive: leader-only cumulative fence + atomic on this half's counter
        if (t < T_STEPS - 1 && tid == 0) {
            fence_gpu();
            atomicAdd(barp, 1ull);
        }

        // overlap with other CTAs' arrival: ys store + next-xp prefetch
        if (tid < 64) {
            const int b = tid >> 1, half = tid & 1;
            float4 v = *(float4*)(Hs + b * 8 + half * 4);
            *(float4*)(ys + ((size_t)t * 64 + bh * 32 + b) * HID + cg * 8 + half * 4) = v;
        }
        {
            const int tn = (t + 1 < T_STEPS) ? t + 1 : t;
            const size_t ncol = (size_t)tn * 64 + bh * 32 + bb;
            #pragma unroll
            for (int gate = 0; gate < 4; gate++)
                xpn[gate] = __ldg(g_xpT + (size_t)(gate * HID + cg * 8 + cc) * TB + ncol);
        }

        // wait: single leader polls this half's counter (tight volatile spin)
        if (t < T_STEPS - 1) {
            if (tid == 0) {
                const unsigned long long tgt =
                    base + (unsigned long long)(t + 1) * GRP_CTAS;
                while (ld_vol_u64(barp) < tgt) { }
                fence_gpu();
            }
            __syncthreads();
        }
    }
}

// ===========================================================================
extern "C" void kernel_launch(void* const* d_in, const int* in_sizes, int n_in,
                              void* d_out, int out_size) {
    (void)in_sizes; (void)n_in; (void)out_size;
    const float* x    = (const float*)d_in[0];
    const float* W_ih = (const float*)d_in[1];
    const float* W_hh = (const float*)d_in[2];
    const float* b_ih = (const float*)d_in[3];
    const float* b_hh = (const float*)d_in[4];
    float* ys = (float*)d_out;

    cudaFuncSetAttribute(xproj_kernel, cudaFuncAttributeMaxDynamicSharedMemorySize, SMEM1);
    cudaFuncSetAttribute(rec_kernel,   cudaFuncAttributeMaxDynamicSharedMemorySize, SMEM2);

    cvt_kernel<<<2048, 256>>>(x, W_ih);
    xproj_kernel<<<4096, 512, SMEM1>>>();
    rec_kernel<<<REC_NCTA, 256, SMEM2>>>(W_hh, b_ih, b_hh, ys);
}